// round 1
// baseline (speedup 1.0000x reference)
#include <cuda_runtime.h>
#include <cuda_bf16.h>
#include <cstdint>

#define N_NODES  8192
#define N_PAIRS  1000000
#define PATH_LEN 8
#define EDGE_DIM 16

// Scratch: per-pair dot values (4 MB). Static device global per harness rules.
__device__ float g_dots[N_PAIRS];

// Pass 1: compute per-pair masked mean dot, stash it in g_dots, and stake a
// claim on the output cell with atomicMax(pair_index+1) on the int-view of
// the (zeroed) output. Max pair index == last write in index order == JAX
// .at[].set semantics for duplicate indices.
__global__ void __launch_bounds__(256)
pass1_kernel(const float* __restrict__ edge_attr,
             const int*   __restrict__ src,
             const int*   __restrict__ dst,
             const int*   __restrict__ paths,
             const float* __restrict__ edge_vector,
             int*         __restrict__ out_i,
             int n_pairs)
{
    int p = blockIdx.x * blockDim.x + threadIdx.x;
    if (p >= n_pairs) return;

    // 8 path edge indices, contiguous 32B -> two int4 loads
    const int4* prow = (const int4*)paths + (size_t)p * 2;
    int4 pa = prow[0];
    int4 pb = prow[1];
    int idxs[PATH_LEN] = {pa.x, pa.y, pa.z, pa.w, pb.x, pb.y, pb.z, pb.w};

    const float4* ea4 = (const float4*)edge_attr;   // row e -> ea4[e*4 .. e*4+3]
    const float4* ev4 = (const float4*)edge_vector; // row l -> ev4[l*4 .. l*4+3]

    float sum = 0.0f;
#pragma unroll
    for (int l = 0; l < PATH_LEN; ++l) {
        int e = idxs[l];
        if (e >= 0) {
            float s = 0.0f;
#pragma unroll
            for (int j = 0; j < 4; ++j) {
                float4 a = __ldg(&ea4[(size_t)e * 4 + j]);  // L2-resident (6.4MB table)
                float4 v = __ldg(&ev4[l * 4 + j]);          // L1-resident (512B)
                s += a.x * v.x + a.y * v.y + a.z * v.z + a.w * v.w;
            }
            sum += s;
        }
    }
    sum *= (1.0f / PATH_LEN);   // mean over full path length, incl. padding
    g_dots[p] = sum;

    int cell = src[p] * N_NODES + dst[p];   // < 2^26, fits int
    atomicMax(&out_i[cell], p + 1);         // cells start at 0; p+1 >= 1
}

// Pass 2: the winning pair (and only it) replaces its claim token with the
// float value. Untouched cells keep the memset 0 == 0.0f.
__global__ void __launch_bounds__(256)
pass2_kernel(const int* __restrict__ src,
             const int* __restrict__ dst,
             float*     __restrict__ out,
             int n_pairs)
{
    int p = blockIdx.x * blockDim.x + threadIdx.x;
    if (p >= n_pairs) return;
    int cell = src[p] * N_NODES + dst[p];
    // Read int-view claim. Only the max pair index matches; a post-overwrite
    // float bit pattern can never alias a value in [1, N_PAIRS].
    const int* out_i = (const int*)out;
    if (out_i[cell] == p + 1) {
        out[cell] = g_dots[p];
    }
}

extern "C" void kernel_launch(void* const* d_in, const int* in_sizes, int n_in,
                              void* d_out, int out_size)
{
    // Inputs per setup_inputs order: [num_nodes?, edge_attr, src, dst, paths, edge_vector]
    // num_nodes may or may not be materialized as a 1-element tensor; detect by size.
    int off = (in_sizes[0] == 1) ? 1 : 0;

    const float* edge_attr   = (const float*)d_in[off + 0];
    const int*   src         = (const int*)  d_in[off + 1];
    const int*   dst         = (const int*)  d_in[off + 2];
    const int*   paths       = (const int*)  d_in[off + 3];
    const float* edge_vector = (const float*)d_in[off + 4];

    float* out = (float*)d_out;

    // Output is poisoned 0xAA — zero it (memset node is graph-capturable).
    cudaMemsetAsync(out, 0, (size_t)out_size * sizeof(float), 0);

    const int n_pairs = in_sizes[off + 1];  // src element count == N_PAIRS
    const int threads = 256;
    const int blocks  = (n_pairs + threads - 1) / threads;

    pass1_kernel<<<blocks, threads>>>(edge_attr, src, dst, paths, edge_vector,
                                      (int*)out, n_pairs);
    pass2_kernel<<<blocks, threads>>>(src, dst, out, n_pairs);
}

// round 2
// speedup vs baseline: 1.3247x; 1.3247x over previous
#include <cuda_runtime.h>
#include <cstdint>

#define N_NODES     8192
#define N_PAIRS_MAX 1000000
#define PATH_LEN    8
#define EDGE_DIM    16
#define MAX_EDGES   100000

#define HASH_BITS   22
#define HASH_SLOTS  (1u << HASH_BITS)
#define HASH_MASK   (HASH_SLOTS - 1u)

// Static device scratch (no allocs allowed).
__device__ float              g_dots[N_PAIRS_MAX];                  // 4 MB
__device__ float              g_T[MAX_EDGES * PATH_LEN];            // 3.2 MB
__device__ unsigned long long g_hash[HASH_SLOTS];                   // 32 MB

// ---------------------------------------------------------------------------
// A: T[e][l] = dot(edge_attr[e], edge_vector[l]).  100k threads, trivial.
// ---------------------------------------------------------------------------
__global__ void __launch_bounds__(256)
precompute_T(const float* __restrict__ edge_attr,
             const float* __restrict__ edge_vector,
             int n_edges)
{
    int e = blockIdx.x * blockDim.x + threadIdx.x;
    if (e >= n_edges) return;

    const float4* ea = (const float4*)edge_attr + (size_t)e * 4;
    float4 a0 = __ldg(&ea[0]), a1 = __ldg(&ea[1]);
    float4 a2 = __ldg(&ea[2]), a3 = __ldg(&ea[3]);

    const float4* ev = (const float4*)edge_vector;
    float t[PATH_LEN];
#pragma unroll
    for (int l = 0; l < PATH_LEN; ++l) {
        float4 v0 = __ldg(&ev[l * 4 + 0]);
        float4 v1 = __ldg(&ev[l * 4 + 1]);
        float4 v2 = __ldg(&ev[l * 4 + 2]);
        float4 v3 = __ldg(&ev[l * 4 + 3]);
        t[l] = a0.x * v0.x + a0.y * v0.y + a0.z * v0.z + a0.w * v0.w
             + a1.x * v1.x + a1.y * v1.y + a1.z * v1.z + a1.w * v1.w
             + a2.x * v2.x + a2.y * v2.y + a2.z * v2.z + a2.w * v2.w
             + a3.x * v3.x + a3.y * v3.y + a3.z * v3.z + a3.w * v3.w;
    }
    float4* tt = (float4*)(g_T + (size_t)e * PATH_LEN);
    tt[0] = make_float4(t[0], t[1], t[2], t[3]);
    tt[1] = make_float4(t[4], t[5], t[6], t[7]);
}

// ---------------------------------------------------------------------------
// C: per-pair masked mean via T-gather, stash in g_dots, claim (cell -> max p)
//    in the L2-resident hash table. Does NOT touch the output buffer.
// ---------------------------------------------------------------------------
__global__ void __launch_bounds__(256)
pair_dots_claim(const int* __restrict__ paths,
                const int* __restrict__ src,
                const int* __restrict__ dst,
                int n_pairs)
{
    int p = blockIdx.x * blockDim.x + threadIdx.x;
    if (p >= n_pairs) return;

    const int4* pr = (const int4*)paths + (size_t)p * 2;
    int4 pa = pr[0];
    int4 pb = pr[1];
    int idxs[PATH_LEN] = {pa.x, pa.y, pa.z, pa.w, pb.x, pb.y, pb.z, pb.w};

    float sum = 0.0f;
#pragma unroll
    for (int l = 0; l < PATH_LEN; ++l) {
        int e = idxs[l];
        if (e >= 0) sum += __ldg(&g_T[(size_t)e * PATH_LEN + l]);
    }
    g_dots[p] = sum * (1.0f / PATH_LEN);

    unsigned cell = (unsigned)src[p] * N_NODES + (unsigned)dst[p]; // < 2^26
    unsigned key  = cell + 1u;                                     // != 0
    unsigned long long want = ((unsigned long long)key << 24) | (unsigned)(p + 1);
    unsigned slot = (cell * 2654435761u) >> (32 - HASH_BITS);

    while (true) {
        unsigned long long cur = g_hash[slot];
        if (cur == 0ULL) {
            unsigned long long prev = atomicCAS(&g_hash[slot], 0ULL, want);
            if (prev == 0ULL) return;
            cur = prev;
        }
        if ((unsigned)(cur >> 24) == key) {        // keys are write-once
            atomicMax(&g_hash[slot], want);        // same key -> compares p+1
            return;
        }
        slot = (slot + 1u) & HASH_MASK;
    }
}

// ---------------------------------------------------------------------------
// D: winner (max pair index per cell, == JAX last-write semantics) writes its
//    value into the zeroed output.
// ---------------------------------------------------------------------------
__global__ void __launch_bounds__(256)
fixup(const int* __restrict__ src,
      const int* __restrict__ dst,
      float* __restrict__ out,
      int n_pairs)
{
    int p = blockIdx.x * blockDim.x + threadIdx.x;
    if (p >= n_pairs) return;

    unsigned cell = (unsigned)src[p] * N_NODES + (unsigned)dst[p];
    unsigned key  = cell + 1u;
    unsigned slot = (cell * 2654435761u) >> (32 - HASH_BITS);

    unsigned winner;
    while (true) {
        unsigned long long cur = g_hash[slot];
        if ((unsigned)(cur >> 24) == key) { winner = (unsigned)(cur & 0xFFFFFFu); break; }
        slot = (slot + 1u) & HASH_MASK;   // entry for this cell must exist
    }
    if (winner == (unsigned)(p + 1)) out[cell] = g_dots[p];
}

// ---------------------------------------------------------------------------
extern "C" void kernel_launch(void* const* d_in, const int* in_sizes, int n_in,
                              void* d_out, int out_size)
{
    int off = (in_sizes[0] == 1) ? 1 : 0;

    const float* edge_attr   = (const float*)d_in[off + 0];
    const int*   src         = (const int*)  d_in[off + 1];
    const int*   dst         = (const int*)  d_in[off + 2];
    const int*   paths       = (const int*)  d_in[off + 3];
    const float* edge_vector = (const float*)d_in[off + 4];
    float* out = (float*)d_out;

    const int n_edges = in_sizes[off + 0] / EDGE_DIM;
    const int n_pairs = in_sizes[off + 1];

    // One-time side stream + events (created outside capture, on the
    // correctness call; reused identically on every call -> deterministic).
    static cudaStream_t s2 = nullptr;
    static cudaEvent_t  evF = nullptr, evJ = nullptr;
    static bool inited = false;
    if (!inited) {
        if (cudaStreamCreateWithFlags(&s2, cudaStreamNonBlocking) != cudaSuccess) s2 = nullptr;
        if (s2) {
            if (cudaEventCreateWithFlags(&evF, cudaEventDisableTiming) != cudaSuccess ||
                cudaEventCreateWithFlags(&evJ, cudaEventDisableTiming) != cudaSuccess) {
                s2 = nullptr;  // fall back to fully serialized on stream 0
            }
        }
        inited = true;
    }

    // Fork: big output memset runs on s2, concurrent with compute on stream 0.
    if (s2) {
        cudaEventRecord(evF, 0);
        cudaStreamWaitEvent(s2, evF, 0);
        cudaMemsetAsync(out, 0, (size_t)out_size * sizeof(float), s2);
        cudaEventRecord(evJ, s2);
    } else {
        cudaMemsetAsync(out, 0, (size_t)out_size * sizeof(float), 0);
    }

    // Main stream: zero hash table, precompute T, dots + claims.
    void* hashp = nullptr;
    cudaGetSymbolAddress(&hashp, g_hash);
    cudaMemsetAsync(hashp, 0, (size_t)HASH_SLOTS * sizeof(unsigned long long), 0);

    precompute_T<<<(n_edges + 255) / 256, 256>>>(edge_attr, edge_vector, n_edges);

    const int blocks = (n_pairs + 255) / 256;
    pair_dots_claim<<<blocks, 256>>>(paths, src, dst, n_pairs);

    // Join: fixup needs both the zeroed output and the claims.
    if (s2) cudaStreamWaitEvent(0, evJ, 0);
    fixup<<<blocks, 256>>>(src, dst, out, n_pairs);
}

// round 3
// speedup vs baseline: 1.4282x; 1.0781x over previous
#include <cuda_runtime.h>
#include <cstdint>

#define N_NODES     8192
#define N_PAIRS_MAX 1000000
#define PATH_LEN    8
#define EDGE_DIM    16
#define MAX_EDGES   100000

#define HASH_BITS   22
#define HASH_SLOTS  (1u << HASH_BITS)
#define HASH_MASK   (HASH_SLOTS - 1u)

// Static device scratch (no allocs allowed).
__device__ float              g_dots[N_PAIRS_MAX];          // 4 MB
__device__ float              g_T[MAX_EDGES * PATH_LEN];    // 3.2 MB
__device__ unsigned long long g_hash[HASH_SLOTS];           // 32 MB

// ---------------------------------------------------------------------------
// T[e][l] = dot(edge_attr[e], edge_vector[l])
// ---------------------------------------------------------------------------
__global__ void __launch_bounds__(256)
precompute_T(const float* __restrict__ edge_attr,
             const float* __restrict__ edge_vector,
             int n_edges)
{
    int e = blockIdx.x * blockDim.x + threadIdx.x;
    if (e >= n_edges) return;

    const float4* ea = (const float4*)edge_attr + (size_t)e * 4;
    float4 a0 = __ldg(&ea[0]), a1 = __ldg(&ea[1]);
    float4 a2 = __ldg(&ea[2]), a3 = __ldg(&ea[3]);

    const float4* ev = (const float4*)edge_vector;
    float t[PATH_LEN];
#pragma unroll
    for (int l = 0; l < PATH_LEN; ++l) {
        float4 v0 = __ldg(&ev[l * 4 + 0]);
        float4 v1 = __ldg(&ev[l * 4 + 1]);
        float4 v2 = __ldg(&ev[l * 4 + 2]);
        float4 v3 = __ldg(&ev[l * 4 + 3]);
        t[l] = a0.x * v0.x + a0.y * v0.y + a0.z * v0.z + a0.w * v0.w
             + a1.x * v1.x + a1.y * v1.y + a1.z * v1.z + a1.w * v1.w
             + a2.x * v2.x + a2.y * v2.y + a2.z * v2.z + a2.w * v2.w
             + a3.x * v3.x + a3.y * v3.y + a3.z * v3.z + a3.w * v3.w;
    }
    float4* tt = (float4*)(g_T + (size_t)e * PATH_LEN);
    tt[0] = make_float4(t[0], t[1], t[2], t[3]);
    tt[1] = make_float4(t[4], t[5], t[6], t[7]);
}

// ---------------------------------------------------------------------------
// Per-pair masked mean via T-gather; claim (cell -> max pair idx) in hash.
// slot entry: key(=cell+1) << 24 | (p+1).  p+1 < 2^20 so fields don't overlap.
// ---------------------------------------------------------------------------
__global__ void __launch_bounds__(256)
pair_dots_claim(const int* __restrict__ paths,
                const int* __restrict__ src,
                const int* __restrict__ dst,
                int n_pairs)
{
    int p = blockIdx.x * blockDim.x + threadIdx.x;
    if (p >= n_pairs) return;

    const int4* pr = (const int4*)paths + (size_t)p * 2;
    int4 pa = pr[0];
    int4 pb = pr[1];
    int idxs[PATH_LEN] = {pa.x, pa.y, pa.z, pa.w, pb.x, pb.y, pb.z, pb.w};

    float sum = 0.0f;
#pragma unroll
    for (int l = 0; l < PATH_LEN; ++l) {
        int e = idxs[l];
        if (e >= 0) sum += __ldg(&g_T[(size_t)e * PATH_LEN + l]);
    }
    g_dots[p] = sum * (1.0f / PATH_LEN);

    unsigned cell = (unsigned)src[p] * N_NODES + (unsigned)dst[p]; // < 2^26
    unsigned key  = cell + 1u;                                     // != 0
    unsigned long long want = ((unsigned long long)key << 24) | (unsigned)(p + 1);
    unsigned slot = (cell * 2654435761u) >> (32 - HASH_BITS);

    while (true) {
        unsigned long long cur = g_hash[slot];
        if (cur == 0ULL) {
            unsigned long long prev = atomicCAS(&g_hash[slot], 0ULL, want);
            if (prev == 0ULL) return;
            cur = prev;
        }
        if ((unsigned)(cur >> 24) == key) {     // keys are write-once
            atomicMax(&g_hash[slot], want);     // same key -> compares p+1
            return;
        }
        slot = (slot + 1u) & HASH_MASK;
    }
}

// ---------------------------------------------------------------------------
// Coalesced sweep of the hash table: every occupied slot IS a winner record
// after all claims resolve (max p per cell == JAX last-write semantics).
// ---------------------------------------------------------------------------
__global__ void __launch_bounds__(256)
fixup_scan(float* __restrict__ out)
{
    unsigned i = blockIdx.x * blockDim.x + threadIdx.x;
    if (i >= HASH_SLOTS) return;
    unsigned long long cur = g_hash[i];
    if (cur != 0ULL) {
        unsigned cell = (unsigned)(cur >> 24) - 1u;
        unsigned p    = (unsigned)(cur & 0xFFFFFFu) - 1u;
        out[cell] = g_dots[p];
    }
}

// ---------------------------------------------------------------------------
extern "C" void kernel_launch(void* const* d_in, const int* in_sizes, int n_in,
                              void* d_out, int out_size)
{
    int off = (in_sizes[0] == 1) ? 1 : 0;

    const float* edge_attr   = (const float*)d_in[off + 0];
    const int*   src         = (const int*)  d_in[off + 1];
    const int*   dst         = (const int*)  d_in[off + 2];
    const int*   paths       = (const int*)  d_in[off + 3];
    const float* edge_vector = (const float*)d_in[off + 4];
    float* out = (float*)d_out;

    const int n_edges = in_sizes[off + 0] / EDGE_DIM;
    const int n_pairs = in_sizes[off + 1];

    // One-time streams/events (created outside graph capture on the
    // correctness call; reused identically every call -> deterministic).
    static cudaStream_t s2 = nullptr, s3 = nullptr;
    static cudaEvent_t  evF = nullptr, evOut = nullptr, evHash = nullptr;
    static bool inited = false;
    if (!inited) {
        bool ok = cudaStreamCreateWithFlags(&s2, cudaStreamNonBlocking) == cudaSuccess
               && cudaStreamCreateWithFlags(&s3, cudaStreamNonBlocking) == cudaSuccess
               && cudaEventCreateWithFlags(&evF,    cudaEventDisableTiming) == cudaSuccess
               && cudaEventCreateWithFlags(&evOut,  cudaEventDisableTiming) == cudaSuccess
               && cudaEventCreateWithFlags(&evHash, cudaEventDisableTiming) == cudaSuccess;
        if (!ok) { s2 = nullptr; s3 = nullptr; }
        inited = true;
    }

    void* hashp = nullptr;
    cudaGetSymbolAddress(&hashp, g_hash);
    const size_t hash_bytes = (size_t)HASH_SLOTS * sizeof(unsigned long long);

    if (s2) {
        // Fork
        cudaEventRecord(evF, 0);
        cudaStreamWaitEvent(s2, evF, 0);
        cudaStreamWaitEvent(s3, evF, 0);
        // s2: big output zero-fill (256 MB), fully overlapped with compute.
        cudaMemsetAsync(out, 0, (size_t)out_size * sizeof(float), s2);
        cudaEventRecord(evOut, s2);
        // s3: hash zero-fill (32 MB), overlapped with precompute_T.
        cudaMemsetAsync(hashp, 0, hash_bytes, s3);
        cudaEventRecord(evHash, s3);

        precompute_T<<<(n_edges + 255) / 256, 256>>>(edge_attr, edge_vector, n_edges);

        cudaStreamWaitEvent(0, evHash, 0);
        pair_dots_claim<<<(n_pairs + 255) / 256, 256>>>(paths, src, dst, n_pairs);

        cudaStreamWaitEvent(0, evOut, 0);
        fixup_scan<<<HASH_SLOTS / 256, 256>>>(out);
    } else {
        // Serialized fallback
        cudaMemsetAsync(out, 0, (size_t)out_size * sizeof(float), 0);
        cudaMemsetAsync(hashp, 0, hash_bytes, 0);
        precompute_T<<<(n_edges + 255) / 256, 256>>>(edge_attr, edge_vector, n_edges);
        pair_dots_claim<<<(n_pairs + 255) / 256, 256>>>(paths, src, dst, n_pairs);
        fixup_scan<<<HASH_SLOTS / 256, 256>>>(out);
    }
}